// round 6
// baseline (speedup 1.0000x reference)
#include <cuda_runtime.h>
#include <cstdint>

#define NN      50000
#define NE      800000
#define MROWS   100000      // B*N rows
#define EPS_BN  1e-5f

// ---------------- scratch (device globals; no allocation allowed) ----------------
__device__ float g_buf1[(size_t)MROWS * 64];   // GEMM outputs (pre-aggregation), layout [(2n+b)][64]
__device__ float g_buf2[(size_t)MROWS * 64];   // post-agg ReLU features, layout [(2n+b)][64]
__device__ float g_deg[NN];
__device__ float g_dinv[NN];
__device__ int   g_cnt[NN];
__device__ int   g_cur[NN];
__device__ int   g_rowptr[NN + 1];
__device__ int   g_csr_src[NE];
__device__ float g_csr_norm[NE];
__device__ float g_bn[4 * 64];                 // [sum1 | sq1 | sum2 | sq2]
__device__ float g_W2p[64 * 64];               // diag(s1) @ W2
__device__ float g_c2[64];                     // t1 @ W2
__device__ float g_wcp[64];                    // s2 .* Wc
__device__ float g_cc[1];                      // t2 @ Wc + bc
__device__ int   g_is64;                       // edge_index dtype flag

// ---------------- dtype detect: int64 edge_index has zero hi-words ----------------
__global__ void k_detect(const int* __restrict__ p) {
    // probe odd 32-bit words of the first 16 "elements"; all-zero => int64
    int ornz = 0;
    #pragma unroll
    for (int i = 1; i < 32; i += 2) ornz |= p[i];
    g_is64 = (ornz == 0) ? 1 : 0;
}

__device__ __forceinline__ int edge_at(const void* ei, long long idx) {
    if (g_is64) return (int)((const long long*)ei)[idx];
    return ((const int*)ei)[idx];
}

// ---------------- init ----------------
__global__ void k_init() {
    int i = blockIdx.x * blockDim.x + threadIdx.x;
    if (i < NN) { g_cnt[i] = 0; g_deg[i] = 1.0f; }   // self-loop weight 1
    if (i < 256) g_bn[i] = 0.f;
}

// ---------------- degree + per-dest edge count ----------------
__global__ void k_deg(const void* __restrict__ ei, const float* __restrict__ ew) {
    int e = blockIdx.x * blockDim.x + threadIdx.x;
    if (e >= NE) return;
    int c = edge_at(ei, (long long)NE + e);
    float w = expf(ew[e]);
    atomicAdd(&g_deg[c], w);
    atomicAdd(&g_cnt[c], 1);
}

// ---------------- single-block exclusive scan (cnt -> rowptr/cur) + dinv ----------------
__global__ void k_scan() {
    __shared__ int warp_sums[32];
    __shared__ int s_carry;
    int tid = threadIdx.x, lane = tid & 31, wid = tid >> 5;
    if (tid == 0) { s_carry = 0; g_rowptr[0] = 0; }
    __syncthreads();
    for (int base = 0; base < NN; base += 1024) {
        int i = base + tid;
        int v = (i < NN) ? g_cnt[i] : 0;
        int x = v;
        #pragma unroll
        for (int off = 1; off < 32; off <<= 1) {
            int y = __shfl_up_sync(0xffffffffu, x, off);
            if (lane >= off) x += y;
        }
        if (lane == 31) warp_sums[wid] = x;
        __syncthreads();
        if (wid == 0) {
            int ws = warp_sums[lane];
            int wx = ws;
            #pragma unroll
            for (int off = 1; off < 32; off <<= 1) {
                int y = __shfl_up_sync(0xffffffffu, wx, off);
                if (lane >= off) wx += y;
            }
            warp_sums[lane] = wx - ws;   // exclusive warp prefix
        }
        __syncthreads();
        int incl = x + warp_sums[wid];
        int carry = s_carry;
        if (i < NN) {
            g_rowptr[i + 1] = carry + incl;
            g_cur[i]        = carry + incl - v;
            g_dinv[i]       = rsqrtf(g_deg[i]);
        }
        __syncthreads();
        if (tid == 1023) s_carry = carry + incl;
        __syncthreads();
    }
}

// ---------------- fill CSR (by destination) ----------------
__global__ void k_fill(const void* __restrict__ ei, const float* __restrict__ ew) {
    int e = blockIdx.x * blockDim.x + threadIdx.x;
    if (e >= NE) return;
    int r = edge_at(ei, e);
    int c = edge_at(ei, (long long)NE + e);
    float w = expf(ew[e]);
    int pos = atomicAdd(&g_cur[c], 1);
    g_csr_src[pos]  = r;
    g_csr_norm[pos] = g_dinv[r] * w * g_dinv[c];
}

// ---------------- SGEMM: C[MROWS][64] = A[MROWS][K] * B[K][64] ----------------
// FIRST=true : A = x (rows m = b*N+n), B = W1 arg, output row remapped to (2n+b), into g_buf1
// FIRST=false: A = g_buf2 (rows already (2n+b)), B = g_W2p, identity map, into g_buf1
template <int K, bool FIRST>
__global__ __launch_bounds__(256) void k_gemm(const float* __restrict__ Aarg,
                                              const float* __restrict__ Barg) {
    __shared__ float As[8][132];
    __shared__ float Bs[8][64];
    const float* A  = FIRST ? Aarg : (const float*)g_buf2;
    const float* Bm = FIRST ? Barg : (const float*)g_W2p;
    float* C = g_buf1;

    const int tid  = threadIdx.x;
    const int bm   = blockIdx.x * 128;
    const int tn   = (tid & 15) * 4;   // 0..60
    const int tm   = (tid >> 4) * 8;   // 0..120
    const int arow = tid >> 1;         // 0..127
    const int akq  = (tid & 1) * 4;    // 0 or 4

    float acc[8][4];
    #pragma unroll
    for (int i = 0; i < 8; i++)
        #pragma unroll
        for (int j = 0; j < 4; j++) acc[i][j] = 0.f;

    for (int k0 = 0; k0 < K; k0 += 8) {
        int gr = bm + arow;
        float4 av = make_float4(0.f, 0.f, 0.f, 0.f);
        if (gr < MROWS) av = *(const float4*)(A + (size_t)gr * K + (k0 + akq));
        As[akq + 0][arow] = av.x;
        As[akq + 1][arow] = av.y;
        As[akq + 2][arow] = av.z;
        As[akq + 3][arow] = av.w;
        if (tid < 128) {
            int bk = tid >> 4, bj = (tid & 15) * 4;
            *(float4*)&Bs[bk][bj] = *(const float4*)(Bm + (size_t)(k0 + bk) * 64 + bj);
        }
        __syncthreads();
        #pragma unroll
        for (int kk = 0; kk < 8; kk++) {
            float4 a0 = *(const float4*)&As[kk][tm];
            float4 a1 = *(const float4*)&As[kk][tm + 4];
            float4 bb = *(const float4*)&Bs[kk][tn];
            float a[8] = {a0.x, a0.y, a0.z, a0.w, a1.x, a1.y, a1.z, a1.w};
            float b[4] = {bb.x, bb.y, bb.z, bb.w};
            #pragma unroll
            for (int i = 0; i < 8; i++)
                #pragma unroll
                for (int j = 0; j < 4; j++)
                    acc[i][j] = fmaf(a[i], b[j], acc[i][j]);
        }
        __syncthreads();
    }

    #pragma unroll
    for (int i = 0; i < 8; i++) {
        int m = bm + tm + i;
        if (m < MROWS) {
            int dst;
            if (FIRST) { int b = m / NN; int n = m - b * NN; dst = n * 2 + b; }
            else       { dst = m; }
            *(float4*)(C + (size_t)dst * 64 + tn) =
                make_float4(acc[i][0], acc[i][1], acc[i][2], acc[i][3]);
        }
    }
}

// ---------------- aggregation: g_buf2[n][:] = relu( A @ g_buf1 + bias (+ rs*c2) ), BN stats ----------------
// warp per destination node (grid-stride); lane handles 4 of 128 combined channels
template <bool L2F>
__global__ __launch_bounds__(256) void k_agg(const float* __restrict__ bias) {
    const int lane = threadIdx.x & 31;
    const int gw = (blockIdx.x * blockDim.x + threadIdx.x) >> 5;
    const int nw = (gridDim.x * blockDim.x) >> 5;
    const int j0 = lane * 4;
    const int ch = j0 & 63;
    const float* __restrict__ hin = g_buf1;
    float* __restrict__ hout = g_buf2;

    float4 bv = *(const float4*)(bias + ch);
    float4 c2v = make_float4(0.f, 0.f, 0.f, 0.f);
    if (L2F) c2v = *(const float4*)(g_c2 + ch);
    float* bs = g_bn + (L2F ? 128 : 0);
    float* bq = g_bn + (L2F ? 192 : 64);

    float4 ps = make_float4(0.f, 0.f, 0.f, 0.f);
    float4 pq = make_float4(0.f, 0.f, 0.f, 0.f);

    for (int n = gw; n < NN; n += nw) {
        int beg = g_rowptr[n], end = g_rowptr[n + 1];
        float4 a0 = make_float4(0.f, 0.f, 0.f, 0.f);
        float4 a1 = make_float4(0.f, 0.f, 0.f, 0.f);
        float rsl = 0.f;
        for (int eb = beg; eb < end; eb += 32) {
            int rem = end - eb;
            int cnt = rem < 32 ? rem : 32;
            int sl = 0; float wl = 0.f;
            if (lane < cnt) { sl = g_csr_src[eb + lane]; wl = g_csr_norm[eb + lane]; }
            rsl += wl;
            int i = 0;
            for (; i + 1 < cnt; i += 2) {
                int   s0 = __shfl_sync(0xffffffffu, sl, i);
                float w0 = __shfl_sync(0xffffffffu, wl, i);
                int   s1 = __shfl_sync(0xffffffffu, sl, i + 1);
                float w1 = __shfl_sync(0xffffffffu, wl, i + 1);
                float4 v0 = *(const float4*)(hin + (size_t)s0 * 128 + j0);
                float4 v1 = *(const float4*)(hin + (size_t)s1 * 128 + j0);
                a0.x = fmaf(w0, v0.x, a0.x); a0.y = fmaf(w0, v0.y, a0.y);
                a0.z = fmaf(w0, v0.z, a0.z); a0.w = fmaf(w0, v0.w, a0.w);
                a1.x = fmaf(w1, v1.x, a1.x); a1.y = fmaf(w1, v1.y, a1.y);
                a1.z = fmaf(w1, v1.z, a1.z); a1.w = fmaf(w1, v1.w, a1.w);
            }
            if (i < cnt) {
                int   s0 = __shfl_sync(0xffffffffu, sl, i);
                float w0 = __shfl_sync(0xffffffffu, wl, i);
                float4 v0 = *(const float4*)(hin + (size_t)s0 * 128 + j0);
                a0.x = fmaf(w0, v0.x, a0.x); a0.y = fmaf(w0, v0.y, a0.y);
                a0.z = fmaf(w0, v0.z, a0.z); a0.w = fmaf(w0, v0.w, a0.w);
            }
        }
        // rowsum of normalized adjacency for this dest (incl. self)
        float rs = rsl;
        #pragma unroll
        for (int off = 16; off; off >>= 1) rs += __shfl_xor_sync(0xffffffffu, rs, off);
        float di = g_dinv[n];
        float ws = di * di;
        rs += ws;
        float4 v = *(const float4*)(hin + (size_t)n * 128 + j0);
        float4 r;
        r.x = a0.x + a1.x + ws * v.x + bv.x;
        r.y = a0.y + a1.y + ws * v.y + bv.y;
        r.z = a0.z + a1.z + ws * v.z + bv.z;
        r.w = a0.w + a1.w + ws * v.w + bv.w;
        if (L2F) {
            r.x = fmaf(rs, c2v.x, r.x); r.y = fmaf(rs, c2v.y, r.y);
            r.z = fmaf(rs, c2v.z, r.z); r.w = fmaf(rs, c2v.w, r.w);
        }
        r.x = fmaxf(r.x, 0.f); r.y = fmaxf(r.y, 0.f);
        r.z = fmaxf(r.z, 0.f); r.w = fmaxf(r.w, 0.f);
        *(float4*)(hout + (size_t)n * 128 + j0) = r;
        ps.x += r.x; ps.y += r.y; ps.z += r.z; ps.w += r.w;
        pq.x = fmaf(r.x, r.x, pq.x); pq.y = fmaf(r.y, r.y, pq.y);
        pq.z = fmaf(r.z, r.z, pq.z); pq.w = fmaf(r.w, r.w, pq.w);
    }
    atomicAdd(&bs[ch + 0], ps.x); atomicAdd(&bs[ch + 1], ps.y);
    atomicAdd(&bs[ch + 2], ps.z); atomicAdd(&bs[ch + 3], ps.w);
    atomicAdd(&bq[ch + 0], pq.x); atomicAdd(&bq[ch + 1], pq.y);
    atomicAdd(&bq[ch + 2], pq.z); atomicAdd(&bq[ch + 3], pq.w);
}

// ---------------- fold BN1 into W2 ----------------
__global__ void k_bnfold1(const float* __restrict__ g1, const float* __restrict__ be1,
                          const float* __restrict__ W2) {
    __shared__ float ss[64], st[64];
    int k = threadIdx.x;  // 64 threads
    const float inv = 1.0f / (float)MROWS;
    float m = g_bn[k] * inv;
    float v = g_bn[64 + k] * inv - m * m;
    float s = g1[k] * rsqrtf(v + EPS_BN);
    float t = fmaf(-m, s, be1[k]);
    ss[k] = s; st[k] = t;
    __syncthreads();
    float c = 0.f;
    for (int r = 0; r < 64; r++) {
        float w = W2[r * 64 + k];
        c = fmaf(st[r], w, c);
        g_W2p[r * 64 + k] = ss[r] * w;
    }
    g_c2[k] = c;
}

// ---------------- fold BN2 into classifier ----------------
__global__ void k_bnfold2(const float* __restrict__ g2, const float* __restrict__ be2,
                          const float* __restrict__ Wc, const float* __restrict__ bc) {
    __shared__ float red[64];
    int k = threadIdx.x;  // 64 threads
    const float inv = 1.0f / (float)MROWS;
    float m = g_bn[128 + k] * inv;
    float v = g_bn[192 + k] * inv - m * m;
    float s = g2[k] * rsqrtf(v + EPS_BN);
    float t = fmaf(-m, s, be2[k]);
    float wc = Wc[k];
    g_wcp[k] = s * wc;
    red[k] = t * wc;
    __syncthreads();
    for (int off = 32; off; off >>= 1) {
        if (k < off) red[k] += red[k + off];
        __syncthreads();
    }
    if (k == 0) g_cc[0] = red[0] + bc[0];
}

// ---------------- classifier: out[b*N+n] = h2bn[n,b,:] . wcp + cc ----------------
__global__ __launch_bounds__(256) void k_cls(float* __restrict__ out) {
    const int lane = threadIdx.x & 31;
    const int gw = (blockIdx.x * blockDim.x + threadIdx.x) >> 5;
    const int nw = (gridDim.x * blockDim.x) >> 5;
    const int j0 = lane * 4;
    float4 wv = *(const float4*)(g_wcp + (j0 & 63));
    float cc = g_cc[0];
    for (int n = gw; n < NN; n += nw) {
        float4 v = *(const float4*)(g_buf2 + (size_t)n * 128 + j0);
        float d = v.x * wv.x + v.y * wv.y + v.z * wv.z + v.w * wv.w;
        d += __shfl_down_sync(0xffffffffu, d, 8, 16);
        d += __shfl_down_sync(0xffffffffu, d, 4, 16);
        d += __shfl_down_sync(0xffffffffu, d, 2, 16);
        d += __shfl_down_sync(0xffffffffu, d, 1, 16);
        if (lane == 0)  out[n]      = d + cc;
        if (lane == 16) out[NN + n] = d + cc;
    }
}

// ---------------- launcher ----------------
extern "C" void kernel_launch(void* const* d_in, const int* in_sizes, int n_in,
                              void* d_out, int out_size) {
    (void)in_sizes; (void)n_in; (void)out_size;
    const float* x    = (const float*)d_in[0];
    const float* ew   = (const float*)d_in[1];
    const float* W1   = (const float*)d_in[2];
    const float* b1   = (const float*)d_in[3];
    const float* W2   = (const float*)d_in[4];
    const float* b2   = (const float*)d_in[5];
    const float* g1   = (const float*)d_in[6];
    const float* be1  = (const float*)d_in[7];
    const float* g2   = (const float*)d_in[8];
    const float* be2  = (const float*)d_in[9];
    const float* Wc   = (const float*)d_in[10];
    const float* bc   = (const float*)d_in[11];
    const void*  eidx = d_in[12];
    float* out = (float*)d_out;

    const int EB = (NE + 255) / 256;
    const int GB = (MROWS + 127) / 128;

    k_detect<<<1, 1>>>((const int*)eidx);
    k_init<<<196, 256>>>();
    k_deg<<<EB, 256>>>(eidx, ew);
    k_scan<<<1, 1024>>>();
    k_fill<<<EB, 256>>>(eidx, ew);

    // layer 1: h = x@W1 (interleaved layout) -> agg+b1+relu+bn1-stats
    k_gemm<128, true><<<GB, 256>>>(x, W1);
    k_agg<false><<<1024, 256>>>(b1);
    k_bnfold1<<<1, 64>>>(g1, be1, W2);

    // layer 2: h = bn1(h1)@W2 (folded) -> agg+b2+rs*c2+relu+bn2-stats
    k_gemm<64, false><<<GB, 256>>>(x, W1);   // args unused for FIRST=false
    k_agg<true><<<1024, 256>>>(b2);
    k_bnfold2<<<1, 64>>>(g2, be2, Wc, bc);

    // classifier
    k_cls<<<1024, 256>>>(out);
}

// round 8
// speedup vs baseline: 4.0201x; 4.0201x over previous
#include <cuda_runtime.h>
#include <cstdint>

#define NN      50000
#define NE      800000
#define MROWS   100000      // B*N rows
#define EPS_BN  1e-5f
#define SCAN_NB 196         // ceil(NN/256)

// ---------------- scratch (device globals; no allocation allowed) ----------------
__device__ float g_buf1[(size_t)MROWS * 64];   // GEMM outputs (pre-aggregation), node-interleaved
__device__ float g_buf2[(size_t)MROWS * 64];   // post-agg ReLU features
__device__ float g_deg[NN];
__device__ float g_dinv[NN];
__device__ int   g_cnt[NN];
__device__ int   g_cur[NN];
__device__ int   g_rowptr[NN + 1];
__device__ int   g_csr_src[NE];
__device__ float g_csr_norm[NE];
__device__ float g_ew[NE];                     // exp(edge_weight), computed once
__device__ float g_bn[4 * 64];                 // [sum1 | sq1 | sum2 | sq2]
__device__ float g_W2p[64 * 64];               // diag(s1) @ W2
__device__ float g_c2[64];                     // t1 @ W2
__device__ float g_wcp[64];                    // s2 .* Wc
__device__ float g_cc[1];                      // t2 @ Wc + bc
__device__ int   g_is64;                       // edge_index dtype flag
__device__ int   g_bsum[256];                  // scan partials
__device__ int   g_boff[256];                  // scan block offsets

// ---------------- dtype detect: int64 edge_index has zero hi-words ----------------
__global__ void k_detect(const int* __restrict__ p) {
    int ornz = 0;
    #pragma unroll
    for (int i = 1; i < 32; i += 2) ornz |= p[i];
    g_is64 = (ornz == 0) ? 1 : 0;
}

__device__ __forceinline__ int edge_at(const void* ei, long long idx) {
    if (g_is64) return (int)((const long long*)ei)[idx];
    return ((const int*)ei)[idx];
}

// ---------------- init ----------------
__global__ void k_init() {
    int i = blockIdx.x * blockDim.x + threadIdx.x;
    if (i < NN) { g_cnt[i] = 0; g_deg[i] = 1.0f; }   // self-loop weight 1
    if (i < 256) g_bn[i] = 0.f;
}

// ---------------- degree + per-dest edge count + exp(ew) ----------------
__global__ void k_deg(const void* __restrict__ ei, const float* __restrict__ ew) {
    int e = blockIdx.x * blockDim.x + threadIdx.x;
    if (e >= NE) return;
    int c = edge_at(ei, (long long)NE + e);
    float w = expf(ew[e]);
    g_ew[e] = w;
    atomicAdd(&g_deg[c], w);
    atomicAdd(&g_cnt[c], 1);
}

// ---------------- decoupled 3-phase scan ----------------
__device__ __forceinline__ int block_incl_scan(int v, int tid) {
    __shared__ int ws[8];
    int lane = tid & 31, wid = tid >> 5;
    int x = v;
    #pragma unroll
    for (int off = 1; off < 32; off <<= 1) {
        int y = __shfl_up_sync(0xffffffffu, x, off);
        if (lane >= off) x += y;
    }
    if (lane == 31) ws[wid] = x;
    __syncthreads();
    if (wid == 0) {
        int wv = (lane < 8) ? ws[lane] : 0;
        int wx = wv;
        #pragma unroll
        for (int off = 1; off < 8; off <<= 1) {
            int y = __shfl_up_sync(0xffffffffu, wx, off);
            if (lane >= off) wx += y;
        }
        if (lane < 8) ws[lane] = wx - wv;     // exclusive warp prefix
    }
    __syncthreads();
    return x + ws[wid];
}

__global__ void k_scanA() {        // per-block reduce of g_cnt
    __shared__ int ws[8];
    int tid = threadIdx.x, lane = tid & 31, wid = tid >> 5;
    int i = blockIdx.x * 256 + tid;
    int v = (i < NN) ? g_cnt[i] : 0;
    #pragma unroll
    for (int off = 16; off; off >>= 1) v += __shfl_xor_sync(0xffffffffu, v, off);
    if (lane == 0) ws[wid] = v;
    __syncthreads();
    if (tid == 0) {
        int s = 0;
        #pragma unroll
        for (int w = 0; w < 8; w++) s += ws[w];
        g_bsum[blockIdx.x] = s;
    }
}

__global__ void k_scanB() {        // exclusive scan of 196 block sums
    int tid = threadIdx.x;
    int v = (tid < SCAN_NB) ? g_bsum[tid] : 0;
    int incl = block_incl_scan(v, tid);
    g_boff[tid] = incl - v;
}

__global__ void k_scanC() {        // local scan + apply
    int tid = threadIdx.x;
    int i = blockIdx.x * 256 + tid;
    int v = (i < NN) ? g_cnt[i] : 0;
    int incl = block_incl_scan(v, tid);
    int base = g_boff[blockIdx.x];
    if (i < NN) {
        g_rowptr[i + 1] = base + incl;
        g_cur[i]        = base + incl - v;
        g_dinv[i]       = rsqrtf(g_deg[i]);
    }
    if (i == 0) g_rowptr[0] = 0;
}

// ---------------- fill CSR (by destination) ----------------
__global__ void k_fill(const void* __restrict__ ei) {
    int e = blockIdx.x * blockDim.x + threadIdx.x;
    if (e >= NE) return;
    int r = edge_at(ei, e);
    int c = edge_at(ei, (long long)NE + e);
    float w = g_ew[e];
    int pos = atomicAdd(&g_cur[c], 1);
    g_csr_src[pos]  = r;
    g_csr_norm[pos] = g_dinv[r] * w * g_dinv[c];
}

// ---------------- SGEMM: C[MROWS][64] = A[MROWS][K] * B[K][64], k-chunk 16 ----------------
// NOTE: As row stride MUST keep 16B alignment for LDS.128 (132 floats = 528B = 33*16).
template <int K, bool FIRST>
__global__ __launch_bounds__(256) void k_gemm(const float* __restrict__ Aarg,
                                              const float* __restrict__ Barg) {
    __shared__ float As[16][132];
    __shared__ float Bs[16][68];
    const float* A  = FIRST ? Aarg : (const float*)g_buf2;
    const float* Bm = FIRST ? Barg : (const float*)g_W2p;
    float* C = g_buf1;

    const int tid  = threadIdx.x;
    const int bm   = blockIdx.x * 128;
    const int tn   = (tid & 15) * 4;   // 0..60
    const int tm   = (tid >> 4) * 8;   // 0..120
    const int arow = tid >> 1;         // 0..127
    const int akq  = (tid & 1) * 8;    // 0 or 8

    float acc[8][4];
    #pragma unroll
    for (int i = 0; i < 8; i++)
        #pragma unroll
        for (int j = 0; j < 4; j++) acc[i][j] = 0.f;

    const int gr = bm + arow;
    const bool grok = (gr < MROWS);
    const float* Arow = A + (size_t)(grok ? gr : 0) * K;

    for (int k0 = 0; k0 < K; k0 += 16) {
        float4 av0 = make_float4(0.f, 0.f, 0.f, 0.f);
        float4 av1 = make_float4(0.f, 0.f, 0.f, 0.f);
        if (grok) {
            av0 = *(const float4*)(Arow + k0 + akq);
            av1 = *(const float4*)(Arow + k0 + akq + 4);
        }
        As[akq + 0][arow] = av0.x; As[akq + 1][arow] = av0.y;
        As[akq + 2][arow] = av0.z; As[akq + 3][arow] = av0.w;
        As[akq + 4][arow] = av1.x; As[akq + 5][arow] = av1.y;
        As[akq + 6][arow] = av1.z; As[akq + 7][arow] = av1.w;
        {
            int bk = tid >> 4, bj = (tid & 15) * 4;   // 16x64 in one shot
            *(float4*)&Bs[bk][bj] = *(const float4*)(Bm + (size_t)(k0 + bk) * 64 + bj);
        }
        __syncthreads();
        #pragma unroll
        for (int kk = 0; kk < 16; kk++) {
            float4 a0 = *(const float4*)&As[kk][tm];
            float4 a1 = *(const float4*)&As[kk][tm + 4];
            float4 bb = *(const float4*)&Bs[kk][tn];
            float a[8] = {a0.x, a0.y, a0.z, a0.w, a1.x, a1.y, a1.z, a1.w};
            float b[4] = {bb.x, bb.y, bb.z, bb.w};
            #pragma unroll
            for (int i = 0; i < 8; i++)
                #pragma unroll
                for (int j = 0; j < 4; j++)
                    acc[i][j] = fmaf(a[i], b[j], acc[i][j]);
        }
        __syncthreads();
    }

    #pragma unroll
    for (int i = 0; i < 8; i++) {
        int m = bm + tm + i;
        if (m < MROWS) {
            int dst;
            if (FIRST) { int b = m / NN; int n = m - b * NN; dst = n * 2 + b; }
            else       { dst = m; }
            *(float4*)(C + (size_t)dst * 64 + tn) =
                make_float4(acc[i][0], acc[i][1], acc[i][2], acc[i][3]);
        }
    }
}

// ---------------- aggregation: g_buf2[n][:] = relu( A @ g_buf1 + bias (+ rs*c2) ), BN stats ----------------
// warp per destination node (grid-stride); lane handles 4 of 128 combined channels.
// Edge chunks padded to a multiple of 4 with (src=n, w=0) so the inner loop always
// issues 4 independent LDG.128 per iteration (MLP=4).
template <bool L2F>
__global__ __launch_bounds__(256) void k_agg(const float* __restrict__ bias) {
    __shared__ float sred[128];
    const int tid = threadIdx.x;
    const int lane = tid & 31;
    const int gw = (blockIdx.x * blockDim.x + tid) >> 5;
    const int nw = (gridDim.x * blockDim.x) >> 5;
    const int j0 = lane * 4;
    const int ch = j0 & 63;
    const float* __restrict__ hin = g_buf1;
    float* __restrict__ hout = g_buf2;

    for (int i = tid; i < 128; i += blockDim.x) sred[i] = 0.f;
    __syncthreads();

    float4 bv = *(const float4*)(bias + ch);
    float4 c2v = make_float4(0.f, 0.f, 0.f, 0.f);
    if (L2F) c2v = *(const float4*)(g_c2 + ch);

    float4 ps = make_float4(0.f, 0.f, 0.f, 0.f);
    float4 pq = make_float4(0.f, 0.f, 0.f, 0.f);

    for (int n = gw; n < NN; n += nw) {
        int beg = g_rowptr[n], end = g_rowptr[n + 1];
        float4 a0 = make_float4(0.f, 0.f, 0.f, 0.f);
        float4 a1 = make_float4(0.f, 0.f, 0.f, 0.f);
        float4 a2 = make_float4(0.f, 0.f, 0.f, 0.f);
        float4 a3 = make_float4(0.f, 0.f, 0.f, 0.f);
        float rsl = 0.f;
        for (int eb = beg; eb < end; eb += 32) {
            int rem = end - eb;
            int cnt = rem < 32 ? rem : 32;
            int sl = n; float wl = 0.f;
            if (lane < cnt) { sl = g_csr_src[eb + lane]; wl = g_csr_norm[eb + lane]; }
            rsl += wl;
            int cnt4 = (cnt + 3) & ~3;
            for (int i = 0; i < cnt4; i += 4) {
                int   s0 = __shfl_sync(0xffffffffu, sl, i);
                int   s1 = __shfl_sync(0xffffffffu, sl, i + 1);
                int   s2 = __shfl_sync(0xffffffffu, sl, i + 2);
                int   s3 = __shfl_sync(0xffffffffu, sl, i + 3);
                float w0 = __shfl_sync(0xffffffffu, wl, i);
                float w1 = __shfl_sync(0xffffffffu, wl, i + 1);
                float w2 = __shfl_sync(0xffffffffu, wl, i + 2);
                float w3 = __shfl_sync(0xffffffffu, wl, i + 3);
                float4 v0 = __ldg((const float4*)(hin + (size_t)s0 * 128 + j0));
                float4 v1 = __ldg((const float4*)(hin + (size_t)s1 * 128 + j0));
                float4 v2 = __ldg((const float4*)(hin + (size_t)s2 * 128 + j0));
                float4 v3 = __ldg((const float4*)(hin + (size_t)s3 * 128 + j0));
                a0.x = fmaf(w0, v0.x, a0.x); a0.y = fmaf(w0, v0.y, a0.y);
                a0.z = fmaf(w0, v0.z, a0.z); a0.w = fmaf(w0, v0.w, a0.w);
                a1.x = fmaf(w1, v1.x, a1.x); a1.y = fmaf(w1, v1.y, a1.y);
                a1.z = fmaf(w1, v1.z, a1.z); a1.w = fmaf(w1, v1.w, a1.w);
                a2.x = fmaf(w2, v2.x, a2.x); a2.y = fmaf(w2, v2.y, a2.y);
                a2.z = fmaf(w2, v2.z, a2.z); a2.w = fmaf(w2, v2.w, a2.w);
                a3.x = fmaf(w3, v3.x, a3.x); a3.y = fmaf(w3, v3.y, a3.y);
                a3.z = fmaf(w3, v3.z, a3.z); a3.w = fmaf(w3, v3.w, a3.w);
            }
        }
        // rowsum of normalized adjacency for this dest (incl. self)
        float rs = rsl;
        #pragma unroll
        for (int off = 16; off; off >>= 1) rs += __shfl_xor_sync(0xffffffffu, rs, off);
        float di = g_dinv[n];
        float ws = di * di;
        rs += ws;
        float4 v = *(const float4*)(hin + (size_t)n * 128 + j0);
        float4 r;
        r.x = (a0.x + a1.x) + (a2.x + a3.x) + ws * v.x + bv.x;
        r.y = (a0.y + a1.y) + (a2.y + a3.y) + ws * v.y + bv.y;
        r.z = (a0.z + a1.z) + (a2.z + a3.z) + ws * v.z + bv.z;
        r.w = (a0.w + a1.w) + (a2.w + a3.w) + ws * v.w + bv.w;
        if (L2F) {
            r.x = fmaf(rs, c2v.x, r.x); r.y = fmaf(rs, c2v.y, r.y);
            r.z = fmaf(rs, c2v.z, r.z); r.w = fmaf(rs, c2v.w, r.w);
        }
        r.x = fmaxf(r.x, 0.f); r.y = fmaxf(r.y, 0.f);
        r.z = fmaxf(r.z, 0.f); r.w = fmaxf(r.w, 0.f);
        *(float4*)(hout + (size_t)n * 128 + j0) = r;
        ps.x += r.x; ps.y += r.y; ps.z += r.z; ps.w += r.w;
        pq.x = fmaf(r.x, r.x, pq.x); pq.y = fmaf(r.y, r.y, pq.y);
        pq.z = fmaf(r.z, r.z, pq.z); pq.w = fmaf(r.w, r.w, pq.w);
    }
    // block-level BN reduction (smem atomics), then 128 global atomics per block
    atomicAdd(&sred[ch + 0], ps.x); atomicAdd(&sred[ch + 1], ps.y);
    atomicAdd(&sred[ch + 2], ps.z); atomicAdd(&sred[ch + 3], ps.w);
    atomicAdd(&sred[64 + ch + 0], pq.x); atomicAdd(&sred[64 + ch + 1], pq.y);
    atomicAdd(&sred[64 + ch + 2], pq.z); atomicAdd(&sred[64 + ch + 3], pq.w);
    __syncthreads();
    if (tid < 128) {
        float val = sred[tid];
        if (val != 0.f) atomicAdd(&g_bn[(L2F ? 128 : 0) + tid], val);
    }
}

// ---------------- fold BN1 into W2 ----------------
__global__ void k_bnfold1(const float* __restrict__ g1, const float* __restrict__ be1,
                          const float* __restrict__ W2) {
    __shared__ float ss[64], st[64];
    int k = threadIdx.x;  // 64 threads
    const float inv = 1.0f / (float)MROWS;
    float m = g_bn[k] * inv;
    float v = g_bn[64 + k] * inv - m * m;
    float s = g1[k] * rsqrtf(v + EPS_BN);
    float t = fmaf(-m, s, be1[k]);
    ss[k] = s; st[k] = t;
    __syncthreads();
    float c = 0.f;
    for (int r = 0; r < 64; r++) {
        float w = W2[r * 64 + k];
        c = fmaf(st[r], w, c);
        g_W2p[r * 64 + k] = ss[r] * w;
    }
    g_c2[k] = c;
}

// ---------------- fold BN2 into classifier ----------------
__global__ void k_bnfold2(const float* __restrict__ g2, const float* __restrict__ be2,
                          const float* __restrict__ Wc, const float* __restrict__ bc) {
    __shared__ float red[64];
    int k = threadIdx.x;  // 64 threads
    const float inv = 1.0f / (float)MROWS;
    float m = g_bn[128 + k] * inv;
    float v = g_bn[192 + k] * inv - m * m;
    float s = g2[k] * rsqrtf(v + EPS_BN);
    float t = fmaf(-m, s, be2[k]);
    float wc = Wc[k];
    g_wcp[k] = s * wc;
    red[k] = t * wc;
    __syncthreads();
    for (int off = 32; off; off >>= 1) {
        if (k < off) red[k] += red[k + off];
        __syncthreads();
    }
    if (k == 0) g_cc[0] = red[0] + bc[0];
}

// ---------------- classifier: out[b*N+n] = h2bn[n,b,:] . wcp + cc ----------------
__global__ __launch_bounds__(256) void k_cls(float* __restrict__ out) {
    const int lane = threadIdx.x & 31;
    const int gw = (blockIdx.x * blockDim.x + threadIdx.x) >> 5;
    const int nw = (gridDim.x * blockDim.x) >> 5;
    const int j0 = lane * 4;
    float4 wv = *(const float4*)(g_wcp + (j0 & 63));
    float cc = g_cc[0];
    for (int n = gw; n < NN; n += nw) {
        float4 v = *(const float4*)(g_buf2 + (size_t)n * 128 + j0);
        float d = v.x * wv.x + v.y * wv.y + v.z * wv.z + v.w * wv.w;
        d += __shfl_down_sync(0xffffffffu, d, 8, 16);
        d += __shfl_down_sync(0xffffffffu, d, 4, 16);
        d += __shfl_down_sync(0xffffffffu, d, 2, 16);
        d += __shfl_down_sync(0xffffffffu, d, 1, 16);
        if (lane == 0)  out[n]      = d + cc;
        if (lane == 16) out[NN + n] = d + cc;
    }
}

// ---------------- launcher ----------------
extern "C" void kernel_launch(void* const* d_in, const int* in_sizes, int n_in,
                              void* d_out, int out_size) {
    (void)in_sizes; (void)n_in; (void)out_size;
    const float* x    = (const float*)d_in[0];
    const float* ew   = (const float*)d_in[1];
    const float* W1   = (const float*)d_in[2];
    const float* b1   = (const float*)d_in[3];
    const float* W2   = (const float*)d_in[4];
    const float* b2   = (const float*)d_in[5];
    const float* g1   = (const float*)d_in[6];
    const float* be1  = (const float*)d_in[7];
    const float* g2   = (const float*)d_in[8];
    const float* be2  = (const float*)d_in[9];
    const float* Wc   = (const float*)d_in[10];
    const float* bc   = (const float*)d_in[11];
    const void*  eidx = d_in[12];
    float* out = (float*)d_out;

    const int EB = (NE + 255) / 256;
    const int GB = (MROWS + 127) / 128;

    k_detect<<<1, 1>>>((const int*)eidx);
    k_init<<<196, 256>>>();
    k_deg<<<EB, 256>>>(eidx, ew);
    k_scanA<<<SCAN_NB, 256>>>();
    k_scanB<<<1, 256>>>();
    k_scanC<<<SCAN_NB, 256>>>();
    k_fill<<<EB, 256>>>(eidx);

    // layer 1: h = x@W1 (interleaved layout) -> agg+b1+relu+bn1-stats
    k_gemm<128, true><<<GB, 256>>>(x, W1);
    k_agg<false><<<2048, 256>>>(b1);
    k_bnfold1<<<1, 64>>>(g1, be1, W2);

    // layer 2: h = bn1(h1)@W2 (folded) -> agg+b2+rs*c2+relu+bn2-stats
    k_gemm<64, false><<<GB, 256>>>(x, W1);   // args unused for FIRST=false
    k_agg<true><<<2048, 256>>>(b2);
    k_bnfold2<<<1, 64>>>(g2, be2, Wc, bc);

    // classifier
    k_cls<<<1024, 256>>>(out);
}